// round 5
// baseline (speedup 1.0000x reference)
#include <cuda_runtime.h>
#include <cstdint>

#define TS 262144
#define HH 90
#define CHUNK 16

typedef unsigned long long u64t;

// inter-layer h streams (layers 0..2 produce) + progress counters
__device__ float g_hbuf[3ull * TS * HH];
__device__ unsigned g_cnt[3][2];

// ---------------- PTX helpers ----------------
__device__ __forceinline__ uint32_t smem_u32(const void* p) { return (uint32_t)__cvta_generic_to_shared(p); }
__device__ __forceinline__ uint32_t mapa_u32(uint32_t a, uint32_t r) {
    uint32_t o; asm("mapa.shared::cluster.u32 %0,%1,%2;" : "=r"(o) : "r"(a), "r"(r)); return o;
}
__device__ __forceinline__ uint32_t ctarank()  { uint32_t r; asm("mov.u32 %0, %%cluster_ctarank;"  : "=r"(r)); return r; }
__device__ __forceinline__ uint32_t nctarank() { uint32_t r; asm("mov.u32 %0, %%cluster_nctarank;" : "=r"(r)); return r; }
__device__ __forceinline__ void fma2(u64t& d, u64t a, u64t b) {
    asm("fma.rn.f32x2 %0,%1,%2,%0;" : "+l"(d) : "l"(a), "l"(b));
}
__device__ __forceinline__ float2 up64(u64t v) {
    float2 r; asm("mov.b64 {%0,%1},%2;" : "=f"(r.x), "=f"(r.y) : "l"(v)); return r;
}
__device__ __forceinline__ u64t pk64(float x, float y) {
    u64t v; asm("mov.b64 %0,{%1,%2};" : "=l"(v) : "f"(x), "f"(y)); return v;
}
__device__ __forceinline__ unsigned ld_acq(const unsigned* p) {
    unsigned v; asm volatile("ld.global.acquire.gpu.b32 %0,[%1];" : "=r"(v) : "l"(p) : "memory"); return v;
}
__device__ __forceinline__ void st_rel(unsigned* p, unsigned v) {
    asm volatile("st.global.release.gpu.b32 [%0],%1;" :: "l"(p), "r"(v) : "memory");
}
__device__ __forceinline__ void st_remote(uint32_t a, float v) {
    asm volatile("st.shared::cluster.f32 [%0],%1;" :: "r"(a), "f"(v) : "memory");
}
__device__ __forceinline__ void mbar_init(uint32_t a, uint32_t c) {
    asm volatile("mbarrier.init.shared.b64 [%0],%1;" :: "r"(a), "r"(c) : "memory");
}
__device__ __forceinline__ void mbar_arrive_remote(uint32_t a) {
    asm volatile("mbarrier.arrive.release.cluster.shared::cluster.b64 _,[%0];" :: "r"(a) : "memory");
}
// bounded parity wait: ~20000 tries x 100us hint worst case, then give up
__device__ __forceinline__ bool mbar_wait_b(uint32_t a, unsigned par) {
    for (int i = 0; i < 20000; i++) {
        uint32_t ok;
        asm volatile(
            "{\n\t.reg .pred P;\n\t"
            "mbarrier.try_wait.parity.acquire.cluster.shared::cta.b64 P,[%1],%2,100000;\n\t"
            "selp.b32 %0,1,0,P;\n\t}"
            : "=r"(ok) : "r"(a), "r"(par) : "memory");
        if (ok) return true;
    }
    return false;
}
// bounded acquire-counter spin
__device__ __forceinline__ bool spin_ge(const unsigned* p, unsigned need, unsigned& avail) {
    for (unsigned i = 0; i < (1u << 22); i++) {
        avail = ld_acq(p);
        if (avail >= need) return true;
    }
    return false;
}
__device__ __forceinline__ void csync() {
    asm volatile("barrier.cluster.arrive.aligned;" ::: "memory");
    asm volatile("barrier.cluster.wait.aligned;" ::: "memory");
}
__device__ __forceinline__ float sigf(float x)   { return 1.f / (1.f + __expf(-x)); }
__device__ __forceinline__ float tanhf_(float x) { return 1.f - 2.f / (__expf(2.f * x) + 1.f); }

// ---------------- per-layer persistent stage (2-CTA cluster) ----------------
template<int LAYER>
__device__ void run_layer(
    const float* __restrict__ x_in,
    const float* __restrict__ h0, const float* __restrict__ c0,
    const float* __restrict__ wih, const float* __restrict__ whh,
    const float* __restrict__ bih, const float* __restrict__ bhh,
    const float* __restrict__ fcw, const float* __restrict__ fcb,
    float* probs, float* zvf)
{
    constexpr bool L0 = (LAYER == 0);
    constexpr bool LL = (LAYER == 3);
    constexpr int KIN = L0 ? 6 : HH;
    constexpr int NPX = L0 ? 4 : 48;   // packed f32x2 x-weights per row
    constexpr int NW  = NPX + 48;

    __shared__ __align__(16) float h_sm[2][96];
    __shared__ __align__(16) float x_sm[2][96];   // layers >= 1
    __shared__ __align__(16) float xr[4][8];      // layer 0 ring
    __shared__ float g_sm[4][48];
    __shared__ __align__(16) float fcw_sm[2][96];
    __shared__ float fcb_sm[2];
    __shared__ __align__(8) u64t mbar;
    __shared__ int s_dead;

    const int tid  = (int)threadIdx.x;
    const int half = (int)ctarank();
    const int peer = half ^ 1;
    const int e0   = half * 45;
    const uint32_t bar      = smem_u32(&mbar);
    const uint32_t bar_peer = mapa_u32(bar, (uint32_t)peer);

    if (tid == 0) s_dead = 0;

    // ---- weights into registers: one full gate row per thread ----
    u64t wk[NW];
    float bias = 0.f, c = 0.f;
    const int gidx = tid / 45, elem = tid % 45;
    if (tid < 180) {
        const int row = gidx * HH + e0 + elem;
#pragma unroll
        for (int p = 0; p < NPX; p++) {
            float a = (2 * p     < KIN) ? wih[row * KIN + 2 * p]     : 0.f;
            float b = (2 * p + 1 < KIN) ? wih[row * KIN + 2 * p + 1] : 0.f;
            wk[p] = pk64(a, b);
        }
#pragma unroll
        for (int p = 0; p < 48; p++) {
            float a = (2 * p     < HH) ? whh[row * HH + 2 * p]     : 0.f;
            float b = (2 * p + 1 < HH) ? whh[row * HH + 2 * p + 1] : 0.f;
            wk[NPX + p] = pk64(a, b);
        }
        bias = bih[row] + bhh[row];
    }
    if (tid < 45) c = c0[LAYER * HH + e0 + tid];

    // ---- smem init ----
    if (tid < 96) {
        h_sm[0][tid] = (tid < HH) ? h0[LAYER * HH + tid] : 0.f;
        h_sm[1][tid] = 0.f;
        x_sm[0][tid] = 0.f; x_sm[1][tid] = 0.f;
        fcw_sm[0][tid] = 0.f; fcw_sm[1][tid] = 0.f;
    }
    if (tid < 32) ((float*)xr)[tid] = 0.f;
    if (LL && half == 0) {
        if (tid < HH) { fcw_sm[0][tid] = fcw[tid]; fcw_sm[1][tid] = fcw[HH + tid]; }
        if (tid < 2)  fcb_sm[tid] = fcb[tid];
    }

    const float* hsrc = L0 ? (const float*)0 : (g_hbuf + (size_t)(LAYER - 1) * TS * HH);
    float*       hdst = LL ? (float*)0       : (g_hbuf + (size_t)LAYER * TS * HH);

    const int  pk = tid - 96;
    const bool pf = (pk >= 0) && (pk < KIN);
    const unsigned* cp = 0;
    unsigned avail = 0;
    float pending = 0.f, nextv = 0.f;

    if (L0) {
        // ring prologue: slots 0..3 <- x_0..x_3, pending <- x_4
        if (tid >= 96 && tid < 120) {
            int s = (tid - 96) / 6, k2 = (tid - 96) % 6;
            xr[s][k2] = x_in[(size_t)s * 6 + k2];
        }
        if (pf) pending = x_in[(size_t)4 * 6 + pk];
    } else {
        if (tid < HH) {
            const unsigned* c0p = &g_cnt[LAYER - 1][(tid < 45) ? 0 : 1];
            unsigned a0 = 0;
            if (!spin_ge(c0p, 1u, a0)) s_dead = 1;
            x_sm[0][tid] = hsrc[tid];
        }
        if (pf) cp = &g_cnt[LAYER - 1][(pk < 45) ? 0 : 1];
    }

    if (tid == 0) mbar_init(bar, 45);
    __syncthreads();
    csync();

    u64t acc0, acc1, acc2, acc3;

    for (int t = 0; t < TS; t++) {
        const int buf = t & 1;
        const int nb  = buf ^ 1;

        // prefetch issue (LDG latency hidden behind the GEMV)
        if (!L0) {
            if (pf && t + 1 < TS) {
                const unsigned need = (unsigned)(t + 2);
                if (avail < need && !s_dead) {
                    if (!spin_ge(cp, need, avail)) s_dead = 1;
                }
                nextv = hsrc[(size_t)(t + 1) * HH + pk];
            }
        } else {
            if (pf && t + 5 < TS) nextv = x_in[(size_t)(t + 5) * 6 + pk];
        }

        // x-part (needs no h_{t-1}: hides the DSMEM exchange)
        if (tid < 180) {
            acc0 = acc1 = acc2 = acc3 = 0ull;
            const ulonglong2* xv = L0 ? (const ulonglong2*)xr[t & 3]
                                      : (const ulonglong2*)x_sm[buf];
#pragma unroll
            for (int q = 0; q < NPX / 2; q++) {
                ulonglong2 v = xv[q];
                if ((q & 1) == 0) { fma2(acc0, wk[2 * q], v.x); fma2(acc1, wk[2 * q + 1], v.y); }
                else              { fma2(acc2, wk[2 * q], v.x); fma2(acc3, wk[2 * q + 1], v.y); }
            }
        }

        // wait for h_{t-1} exchange (phase t-1)
        if (t && !s_dead) {
            if (!mbar_wait_b(bar, (unsigned)((t - 1) & 1))) s_dead = 1;
        }

        // h-part + gate preactivation
        if (tid < 180) {
            const ulonglong2* hv = (const ulonglong2*)h_sm[buf];
#pragma unroll
            for (int q = 0; q < 24; q++) {
                ulonglong2 v = hv[q];
                if ((q & 1) == 0) { fma2(acc0, wk[NPX + 2 * q], v.x); fma2(acc1, wk[NPX + 2 * q + 1], v.y); }
                else              { fma2(acc2, wk[NPX + 2 * q], v.x); fma2(acc3, wk[NPX + 2 * q + 1], v.y); }
            }
            float2 s0 = up64(acc0), s1 = up64(acc1), s2 = up64(acc2), s3 = up64(acc3);
            g_sm[gidx][elem] = bias + ((s0.x + s0.y) + (s1.x + s1.y))
                                    + ((s2.x + s2.y) + (s3.x + s3.y));
        }
        __syncthreads();

        // combine: threads 0..44 own h/c elements [e0, e0+45)
        if (tid < 45) {
            float iv = sigf(g_sm[0][tid]);
            float fv = sigf(g_sm[1][tid]);
            float gv = tanhf_(g_sm[2][tid]);
            float ov = sigf(g_sm[3][tid]);
            c = fv * c + iv * gv;
            float h = ov * tanhf_(c);
            h_sm[nb][e0 + tid] = h;
            st_remote(mapa_u32(smem_u32(&h_sm[nb][e0 + tid]), (uint32_t)peer), h);
            mbar_arrive_remote(bar_peer);           // release: orders this thread's DSMEM write
            if (!LL) hdst[(size_t)t * HH + e0 + tid] = h;
        }

        // FC + softmax + argmax on h_{t-1} (layer 3, CTA 0, warp 2)
        if (LL && half == 0 && t >= 1 && tid >= 64 && tid < 96) {
            const int j = tid - 64;
            const float* hb = h_sm[buf];
            float p0 = 0.f, p1 = 0.f;
#pragma unroll
            for (int kk = 0; kk < 3; kk++) {
                int k = j + 32 * kk;                 // pads [90..95] zero
                float hv = hb[k];
                p0 = fmaf(fcw_sm[0][k], hv, p0);
                p1 = fmaf(fcw_sm[1][k], hv, p1);
            }
#pragma unroll
            for (int off = 16; off; off >>= 1) {
                p0 += __shfl_down_sync(0xffffffffu, p0, off);
                p1 += __shfl_down_sync(0xffffffffu, p1, off);
            }
            if (j == 0) {
                float l0 = p0 + fcb_sm[0], l1 = p1 + fcb_sm[1];
                float m = fmaxf(l0, l1);
                float ea = __expf(l0 - m), eb = __expf(l1 - m);
                float inv = 1.f / (ea + eb);
                float2 pr; pr.x = ea * inv; pr.y = eb * inv;
                *(float2*)(probs + 2 * (size_t)(t - 1)) = pr;
                if (zvf) zvf[t - 1] = (l1 > l0) ? 1.f : 0.f;
            }
        }

        // prefetch store
        if (!L0) {
            if (pf && t + 1 < TS) x_sm[nb][pk] = nextv;
        } else {
            if (pf && t + 4 < TS) xr[t & 3][pk] = pending;
            pending = nextv;
        }
        __syncthreads();

        // publish progress to consumer layer (chunked)
        if (!LL && tid == 0 && (t & (CHUNK - 1)) == (CHUNK - 1))
            st_rel(&g_cnt[LAYER][half], (unsigned)(t + 1));
    }

    // final FC for h_{T-1}
    if (LL && half == 0) {
        if (!s_dead) mbar_wait_b(bar, (unsigned)((TS - 1) & 1));
        if (tid >= 64 && tid < 96) {
            const int j = tid - 64;
            const float* hb = h_sm[TS & 1];
            float p0 = 0.f, p1 = 0.f;
#pragma unroll
            for (int kk = 0; kk < 3; kk++) {
                int k = j + 32 * kk;
                float hv = hb[k];
                p0 = fmaf(fcw_sm[0][k], hv, p0);
                p1 = fmaf(fcw_sm[1][k], hv, p1);
            }
#pragma unroll
            for (int off = 16; off; off >>= 1) {
                p0 += __shfl_down_sync(0xffffffffu, p0, off);
                p1 += __shfl_down_sync(0xffffffffu, p1, off);
            }
            if (j == 0) {
                float l0 = p0 + fcb_sm[0], l1 = p1 + fcb_sm[1];
                float m = fmaxf(l0, l1);
                float ea = __expf(l0 - m), eb = __expf(l1 - m);
                float inv = 1.f / (ea + eb);
                float2 pr; pr.x = ea * inv; pr.y = eb * inv;
                *(float2*)(probs + 2 * (size_t)(TS - 1)) = pr;
                if (zvf) zvf[TS - 1] = (l1 > l0) ? 1.f : 0.f;
            }
        }
    }
    csync();
}

// ---------------- kernels ----------------
__global__ void lstm_init_kernel() {
    if (threadIdx.x < 6) (&g_cnt[0][0])[threadIdx.x] = 0u;
}

__global__ void __cluster_dims__(2, 1, 1) __launch_bounds__(192, 1)
lstm_pipe_kernel(
    const float* __restrict__ x,
    const float* __restrict__ h0,  const float* __restrict__ c0,
    const float* __restrict__ wih0, const float* __restrict__ wih1,
    const float* __restrict__ wih2, const float* __restrict__ wih3,
    const float* __restrict__ whh,
    const float* __restrict__ bih, const float* __restrict__ bhh,
    const float* __restrict__ fcw, const float* __restrict__ fcb,
    float* probs, float* zvf)
{
    if (nctarank() != 2) return;   // clusters broken -> fast visible failure, no hang
    const int layer = (int)(blockIdx.x >> 1);
    if (layer == 0)
        run_layer<0>(x, h0, c0, wih0, whh + 0 * 360 * HH, bih + 0 * 360, bhh + 0 * 360,
                     fcw, fcb, probs, zvf);
    else if (layer == 1)
        run_layer<1>(x, h0, c0, wih1, whh + 1 * 360 * HH, bih + 1 * 360, bhh + 1 * 360,
                     fcw, fcb, probs, zvf);
    else if (layer == 2)
        run_layer<2>(x, h0, c0, wih2, whh + 2 * 360 * HH, bih + 2 * 360, bhh + 2 * 360,
                     fcw, fcb, probs, zvf);
    else
        run_layer<3>(x, h0, c0, wih3, whh + 3 * 360 * HH, bih + 3 * 360, bhh + 3 * 360,
                     fcw, fcb, probs, zvf);
}

extern "C" void kernel_launch(void* const* d_in, const int* in_sizes, int n_in,
                              void* d_out, int out_size) {
    const float* x    = (const float*)d_in[0];
    const float* h0   = (const float*)d_in[1];
    const float* c0   = (const float*)d_in[2];
    const float* wih0 = (const float*)d_in[3];
    const float* wih1 = (const float*)d_in[4];
    const float* wih2 = (const float*)d_in[5];
    const float* wih3 = (const float*)d_in[6];
    const float* whh  = (const float*)d_in[7];
    const float* bih  = (const float*)d_in[8];
    const float* bhh  = (const float*)d_in[9];
    const float* fcw  = (const float*)d_in[10];
    const float* fcb  = (const float*)d_in[11];

    float* out   = (float*)d_out;
    float* probs = out;
    float* zvf   = (out_size >= 3 * TS) ? (out + 2ull * TS) : (float*)0;

    lstm_init_kernel<<<1, 32>>>();

    // explicit cluster launch (the examples never rely on __cluster_dims__ + <<< >>>)
    cudaLaunchConfig_t cfg = {};
    cfg.gridDim  = dim3(8, 1, 1);
    cfg.blockDim = dim3(192, 1, 1);
    cfg.dynamicSmemBytes = 0;
    cfg.stream = 0;
    cudaLaunchAttribute attrs[1];
    attrs[0].id = cudaLaunchAttributeClusterDimension;
    attrs[0].val.clusterDim.x = 2;
    attrs[0].val.clusterDim.y = 1;
    attrs[0].val.clusterDim.z = 1;
    cfg.attrs = attrs;
    cfg.numAttrs = 1;
    cudaLaunchKernelEx(&cfg, lstm_pipe_kernel,
                       x, h0, c0, wih0, wih1, wih2, wih3,
                       whh, bih, bhh, fcw, fcb, probs, zvf);
}

// round 15
// speedup vs baseline: 1.0619x; 1.0619x over previous
#include <cuda_runtime.h>
#include <cstdint>

#define TS 262144
#define HH 90
#define CHUNK 2

typedef unsigned long long u64t;

// inter-layer h streams (layers 0..2 produce) + progress counters
__device__ float g_hbuf[3ull * TS * HH];
__device__ unsigned g_cnt[3][2];

// ---------------- PTX helpers ----------------
__device__ __forceinline__ uint32_t smem_u32(const void* p) { return (uint32_t)__cvta_generic_to_shared(p); }
__device__ __forceinline__ uint32_t mapa_u32(uint32_t a, uint32_t r) {
    uint32_t o; asm("mapa.shared::cluster.u32 %0,%1,%2;" : "=r"(o) : "r"(a), "r"(r)); return o;
}
__device__ __forceinline__ uint32_t ctarank()  { uint32_t r; asm("mov.u32 %0, %%cluster_ctarank;"  : "=r"(r)); return r; }
__device__ __forceinline__ uint32_t nctarank() { uint32_t r; asm("mov.u32 %0, %%cluster_nctarank;" : "=r"(r)); return r; }
__device__ __forceinline__ void fma2(u64t& d, u64t a, u64t b) {
    asm("fma.rn.f32x2 %0,%1,%2,%0;" : "+l"(d) : "l"(a), "l"(b));
}
__device__ __forceinline__ float2 up64(u64t v) {
    float2 r; asm("mov.b64 {%0,%1},%2;" : "=f"(r.x), "=f"(r.y) : "l"(v)); return r;
}
__device__ __forceinline__ u64t pk64(float x, float y) {
    u64t v; asm("mov.b64 %0,{%1,%2};" : "=l"(v) : "f"(x), "f"(y)); return v;
}
__device__ __forceinline__ unsigned ld_acq(const unsigned* p) {
    unsigned v; asm volatile("ld.global.acquire.gpu.b32 %0,[%1];" : "=r"(v) : "l"(p) : "memory"); return v;
}
__device__ __forceinline__ void st_rel(unsigned* p, unsigned v) {
    asm volatile("st.global.release.gpu.b32 [%0],%1;" :: "l"(p), "r"(v) : "memory");
}
__device__ __forceinline__ void st_remote(uint32_t a, float v) {
    asm volatile("st.shared::cluster.f32 [%0],%1;" :: "r"(a), "f"(v) : "memory");
}
__device__ __forceinline__ void mbar_init(uint32_t a, uint32_t c) {
    asm volatile("mbarrier.init.shared.b64 [%0],%1;" :: "r"(a), "r"(c) : "memory");
}
__device__ __forceinline__ void mbar_arrive_remote(uint32_t a) {
    asm volatile("mbarrier.arrive.release.cluster.shared::cluster.b64 _,[%0];" :: "r"(a) : "memory");
}
// bounded parity wait
__device__ __forceinline__ bool mbar_wait_b(uint32_t a, unsigned par) {
    for (int i = 0; i < 20000; i++) {
        uint32_t ok;
        asm volatile(
            "{\n\t.reg .pred P;\n\t"
            "mbarrier.try_wait.parity.acquire.cluster.shared::cta.b64 P,[%1],%2,100000;\n\t"
            "selp.b32 %0,1,0,P;\n\t}"
            : "=r"(ok) : "r"(a), "r"(par) : "memory");
        if (ok) return true;
    }
    return false;
}
// bounded acquire-counter spin
__device__ __forceinline__ bool spin_ge(const unsigned* p, unsigned need, unsigned& avail) {
    for (unsigned i = 0; i < (1u << 22); i++) {
        avail = ld_acq(p);
        if (avail >= need) return true;
    }
    return false;
}
__device__ __forceinline__ float sigf(float x)   { return 1.f / (1.f + __expf(-x)); }
__device__ __forceinline__ float tanhf_(float x) { return 1.f - 2.f / (__expf(2.f * x) + 1.f); }

// ---------------- per-layer persistent stage (2-CTA cluster, K-split GEMV) ----------------
// 384 threads: 0..179   = khalf0 rows 0..179 (input slice [0,48))
//              180..359 = khalf1 rows 0..179 (input slice [48,96))
//              360..383 = prefetch warp (off the GEMV critical path)
template<int LAYER>
__device__ void run_layer(
    const float* __restrict__ x_in,
    const float* __restrict__ h0, const float* __restrict__ c0,
    const float* __restrict__ wih, const float* __restrict__ whh,
    const float* __restrict__ bih, const float* __restrict__ bhh,
    const float* __restrict__ fcw, const float* __restrict__ fcb,
    float* probs, float* zvf)
{
    constexpr bool L0 = (LAYER == 0);
    constexpr bool LL = (LAYER == 3);
    constexpr int KIN  = L0 ? 6 : HH;
    constexpr int NPXH = L0 ? 3 : 24;   // packed x-weight pairs per thread (per K-half)
    constexpr int NW   = NPXH + 24;

    __shared__ __align__(16) float h_sm[2][96];
    __shared__ __align__(16) float x_sm[2][96];   // layers >= 1
    __shared__ __align__(16) float xr[4][8];      // layer 0 ring
    __shared__ float g2[2][184];                  // K-half partials
    __shared__ __align__(16) float fcw_sm[2][96];
    __shared__ float fcb_sm[2];
    __shared__ __align__(8) u64t mbar;
    __shared__ int s_dead;

    const int tid  = (int)threadIdx.x;
    const int half = (int)ctarank();
    const int peer = half ^ 1;
    const int e0   = half * 45;
    const uint32_t bar      = smem_u32(&mbar);
    const uint32_t bar_peer = mapa_u32(bar, (uint32_t)peer);

    if (tid == 0) s_dead = 0;

    const bool  isg   = (tid < 360);
    const int   r     = isg ? (tid < 180 ? tid : tid - 180) : 0;  // row within CTA
    const int   khalf = (tid >= 180 && tid < 360) ? 1 : 0;
    const int   kbase = khalf * 48;                               // float offset of slice

    // ---- weights into registers: one gate-row K-half per thread ----
    u64t wk[NW];
    float bias = 0.f, c = 0.f;
    if (isg) {
        const int row = (r / 45) * HH + e0 + (r % 45);
#pragma unroll
        for (int p = 0; p < NPXH; p++) {
            int col0 = (L0 ? 0 : kbase) + 2 * p;       // L0: khalf1 gets zeros
            float a = (!(L0 && khalf) && col0     < KIN) ? wih[row * KIN + col0]     : 0.f;
            float b = (!(L0 && khalf) && col0 + 1 < KIN) ? wih[row * KIN + col0 + 1] : 0.f;
            wk[p] = pk64(a, b);
        }
#pragma unroll
        for (int p = 0; p < 24; p++) {
            int col0 = kbase + 2 * p;
            float a = (col0     < HH) ? whh[row * HH + col0]     : 0.f;
            float b = (col0 + 1 < HH) ? whh[row * HH + col0 + 1] : 0.f;
            wk[NPXH + p] = pk64(a, b);
        }
        bias = (khalf == 0) ? (bih[row] + bhh[row]) : 0.f;
    }
    if (tid < 45) c = c0[LAYER * HH + e0 + tid];

    // ---- smem zero/const init (epoch 1) ----
    if (tid < 96) {
        h_sm[0][tid] = (tid < HH) ? h0[LAYER * HH + tid] : 0.f;
        h_sm[1][tid] = 0.f;
        x_sm[0][tid] = 0.f; x_sm[1][tid] = 0.f;
        fcw_sm[0][tid] = 0.f; fcw_sm[1][tid] = 0.f;
    }
    if (tid < 32) ((float*)xr)[tid] = 0.f;
    if (LL && half == 0) {
        if (tid < HH) { fcw_sm[0][tid] = fcw[tid]; fcw_sm[1][tid] = fcw[HH + tid]; }
        if (tid < 2)  fcb_sm[tid] = fcb[tid];
    }
    __syncthreads();   // RACE FIX: order zero-init before prologue writes below

    const float* hsrc = L0 ? (const float*)0 : (g_hbuf + (size_t)(LAYER - 1) * TS * HH);
    float*       hdst = LL ? (float*)0       : (g_hbuf + (size_t)LAYER * TS * HH);

    // prefetch warp state
    const int  q   = tid - 360;               // 0..23 when prefetch
    const bool pfw = (q >= 0);
    unsigned avail0 = 0, avail1 = 0;
    float pending = 0.f, nxt0 = 0.f, nxt1 = 0.f, nxt2 = 0.f, nxt3 = 0.f;

    if (L0) {
        // ring prologue (epoch 2): slots 0..3 <- x_0..x_3, pending <- x_4
        if (tid >= 96 && tid < 120) {
            int s = (tid - 96) / 6, k2 = (tid - 96) % 6;
            xr[s][k2] = x_in[(size_t)s * 6 + k2];
        }
        if (pfw && q < 6) pending = x_in[(size_t)4 * 6 + q];
    } else {
        if (tid < HH) {
            const unsigned* c0p = &g_cnt[LAYER - 1][(tid < 45) ? 0 : 1];
            unsigned a0 = 0;
            if (!spin_ge(c0p, 1u, a0)) s_dead = 1;
            x_sm[0][tid] = hsrc[tid];
        }
    }

    if (tid == 0) mbar_init(bar, 45);
    __syncthreads();
    asm volatile("barrier.cluster.arrive.aligned;" ::: "memory");
    asm volatile("barrier.cluster.wait.aligned;" ::: "memory");

    for (int t = 0; t < TS; t++) {
        const int buf = t & 1;
        const int nb  = buf ^ 1;

        // ---- prefetch warp: issue loads for x_{t+1} (L>=1) / x_{t+5} (L0) ----
        if (pfw) {
            if (!L0) {
                if (t + 1 < TS) {
                    const unsigned need = (unsigned)(t + 2);
                    if (!s_dead) {
                        if (avail0 < need && !spin_ge(&g_cnt[LAYER - 1][0], need, avail0)) s_dead = 1;
                        if (avail1 < need && !spin_ge(&g_cnt[LAYER - 1][1], need, avail1)) s_dead = 1;
                    }
                    const float* src = hsrc + (size_t)(t + 1) * HH;
                    nxt0 = src[q];
                    nxt1 = src[24 + q];
                    nxt2 = src[48 + q];
                    if (q < 18) nxt3 = src[72 + q];
                }
            } else {
                if (q < 6 && t + 5 < TS) nxt0 = x_in[(size_t)(t + 5) * 6 + q];
            }
        }

        u64t acc0 = 0ull, acc1 = 0ull, acc2 = 0ull, acc3 = 0ull;

        // ---- x-part (no h dependency; hides peer's DSMEM exchange) ----
        if (isg) {
            if (L0) {
                const u64t* xv = (const u64t*)xr[t & 3];
#pragma unroll
                for (int p = 0; p < 3; p++) fma2(acc0, wk[p], xv[p]);
            } else {
                const ulonglong2* xv = (const ulonglong2*)&x_sm[buf][kbase];
#pragma unroll
                for (int qq = 0; qq < 12; qq++) {
                    ulonglong2 v = xv[qq];
                    if ((qq & 1) == 0) { fma2(acc0, wk[2 * qq], v.x); fma2(acc1, wk[2 * qq + 1], v.y); }
                    else               { fma2(acc2, wk[2 * qq], v.x); fma2(acc3, wk[2 * qq + 1], v.y); }
                }
            }
        }

        // ---- wait for h_{t-1} exchange ----
        if (t && !s_dead) {
            if (!mbar_wait_b(bar, (unsigned)((t - 1) & 1))) s_dead = 1;
        }

        // ---- h-part + partial write ----
        if (isg) {
            const ulonglong2* hv = (const ulonglong2*)&h_sm[buf][kbase];
#pragma unroll
            for (int qq = 0; qq < 12; qq++) {
                ulonglong2 v = hv[qq];
                if ((qq & 1) == 0) { fma2(acc0, wk[NPXH + 2 * qq], v.x); fma2(acc1, wk[NPXH + 2 * qq + 1], v.y); }
                else               { fma2(acc2, wk[NPXH + 2 * qq], v.x); fma2(acc3, wk[NPXH + 2 * qq + 1], v.y); }
            }
            float2 s0 = up64(acc0), s1 = up64(acc1), s2 = up64(acc2), s3 = up64(acc3);
            g2[khalf][r] = bias + ((s0.x + s0.y) + (s1.x + s1.y))
                                + ((s2.x + s2.y) + (s3.x + s3.y));
        }
        __syncthreads();

        // ---- combine: threads 0..44 own h/c elements [e0, e0+45) ----
        if (tid < 45) {
            float gi = g2[0][tid]        + g2[1][tid];
            float gf = g2[0][45 + tid]   + g2[1][45 + tid];
            float gg = g2[0][90 + tid]   + g2[1][90 + tid];
            float go = g2[0][135 + tid]  + g2[1][135 + tid];
            float iv = sigf(gi), fv = sigf(gf), gv = tanhf_(gg), ov = sigf(go);
            c = fv * c + iv * gv;
            float h = ov * tanhf_(c);
            h_sm[nb][e0 + tid] = h;
            st_remote(mapa_u32(smem_u32(&h_sm[nb][e0 + tid]), (uint32_t)peer), h);
            if (!LL) hdst[(size_t)t * HH + e0 + tid] = h;
        }

        // ---- FC + softmax + argmax on h_{t-1} (layer 3, CTA 0, warp 2) ----
        if (LL && half == 0 && t >= 1 && tid >= 64 && tid < 96) {
            const int j = tid - 64;
            const float* hb = h_sm[buf];
            float p0 = 0.f, p1 = 0.f;
#pragma unroll
            for (int kk = 0; kk < 3; kk++) {
                int k = j + 32 * kk;
                float hv = hb[k];
                p0 = fmaf(fcw_sm[0][k], hv, p0);
                p1 = fmaf(fcw_sm[1][k], hv, p1);
            }
#pragma unroll
            for (int off = 16; off; off >>= 1) {
                p0 += __shfl_down_sync(0xffffffffu, p0, off);
                p1 += __shfl_down_sync(0xffffffffu, p1, off);
            }
            if (j == 0) {
                float l0 = p0 + fcb_sm[0], l1 = p1 + fcb_sm[1];
                float m = fmaxf(l0, l1);
                float ea = __expf(l0 - m), eb = __expf(l1 - m);
                float inv = 1.f / (ea + eb);
                float2 pr; pr.x = ea * inv; pr.y = eb * inv;
                *(float2*)(probs + 2 * (size_t)(t - 1)) = pr;
                if (zvf) zvf[t - 1] = (l1 > l0) ? 1.f : 0.f;
            }
        }

        // ---- prefetch store ----
        if (pfw) {
            if (!L0) {
                if (t + 1 < TS) {
                    x_sm[nb][q]      = nxt0;
                    x_sm[nb][24 + q] = nxt1;
                    x_sm[nb][48 + q] = nxt2;
                    if (q < 18) x_sm[nb][72 + q] = nxt3;
                }
            } else {
                if (q < 6) {
                    if (t + 4 < TS) xr[t & 3][q] = pending;
                    pending = nxt0;
                }
            }
        }
        __syncthreads();

        // RACE FIX: release peer only after ALL step-t reads (incl. FC warp) are done.
        // Per-thread program order still orders each tid<45's DSMEM store before its arrive.
        if (tid < 45) mbar_arrive_remote(bar_peer);

        // ---- publish progress to consumer layer (chunked) ----
        if (!LL && tid == 0 && (t & (CHUNK - 1)) == (CHUNK - 1))
            st_rel(&g_cnt[LAYER][half], (unsigned)(t + 1));
    }

    // final FC for h_{T-1}
    if (LL && half == 0) {
        if (!s_dead) mbar_wait_b(bar, (unsigned)((TS - 1) & 1));
        if (tid >= 64 && tid < 96) {
            const int j = tid - 64;
            const float* hb = h_sm[TS & 1];
            float p0 = 0.f, p1 = 0.f;
#pragma unroll
            for (int kk = 0; kk < 3; kk++) {
                int k = j + 32 * kk;
                float hv = hb[k];
                p0 = fmaf(fcw_sm[0][k], hv, p0);
                p1 = fmaf(fcw_sm[1][k], hv, p1);
            }
#pragma unroll
            for (int off = 16; off; off >>= 1) {
                p0 += __shfl_down_sync(0xffffffffu, p0, off);
                p1 += __shfl_down_sync(0xffffffffu, p1, off);
            }
            if (j == 0) {
                float l0 = p0 + fcb_sm[0], l1 = p1 + fcb_sm[1];
                float m = fmaxf(l0, l1);
                float ea = __expf(l0 - m), eb = __expf(l1 - m);
                float inv = 1.f / (ea + eb);
                float2 pr; pr.x = ea * inv; pr.y = eb * inv;
                *(float2*)(probs + 2 * (size_t)(TS - 1)) = pr;
                if (zvf) zvf[TS - 1] = (l1 > l0) ? 1.f : 0.f;
            }
        }
    }
    asm volatile("barrier.cluster.arrive.aligned;" ::: "memory");
    asm volatile("barrier.cluster.wait.aligned;" ::: "memory");
}

// ---------------- kernels ----------------
__global__ void lstm_init_kernel() {
    if (threadIdx.x < 6) (&g_cnt[0][0])[threadIdx.x] = 0u;
}

__global__ void __cluster_dims__(2, 1, 1) __launch_bounds__(384, 1)
lstm_pipe_kernel(
    const float* __restrict__ x,
    const float* __restrict__ h0,  const float* __restrict__ c0,
    const float* __restrict__ wih0, const float* __restrict__ wih1,
    const float* __restrict__ wih2, const float* __restrict__ wih3,
    const float* __restrict__ whh,
    const float* __restrict__ bih, const float* __restrict__ bhh,
    const float* __restrict__ fcw, const float* __restrict__ fcb,
    float* probs, float* zvf)
{
    if (nctarank() != 2) return;   // clusters broken -> fast visible failure, no hang
    const int layer = (int)(blockIdx.x >> 1);
    if (layer == 0)
        run_layer<0>(x, h0, c0, wih0, whh + 0 * 360 * HH, bih + 0 * 360, bhh + 0 * 360,
                     fcw, fcb, probs, zvf);
    else if (layer == 1)
        run_layer<1>(x, h0, c0, wih1, whh + 1 * 360 * HH, bih + 1 * 360, bhh + 1 * 360,
                     fcw, fcb, probs, zvf);
    else if (layer == 2)
        run_layer<2>(x, h0, c0, wih2, whh + 2 * 360 * HH, bih + 2 * 360, bhh + 2 * 360,
                     fcw, fcb, probs, zvf);
    else
        run_layer<3>(x, h0, c0, wih3, whh + 3 * 360 * HH, bih + 3 * 360, bhh + 3 * 360,
                     fcw, fcb, probs, zvf);
}

extern "C" void kernel_launch(void* const* d_in, const int* in_sizes, int n_in,
                              void* d_out, int out_size) {
    const float* x    = (const float*)d_in[0];
    const float* h0   = (const float*)d_in[1];
    const float* c0   = (const float*)d_in[2];
    const float* wih0 = (const float*)d_in[3];
    const float* wih1 = (const float*)d_in[4];
    const float* wih2 = (const float*)d_in[5];
    const float* wih3 = (const float*)d_in[6];
    const float* whh  = (const float*)d_in[7];
    const float* bih  = (const float*)d_in[8];
    const float* bhh  = (const float*)d_in[9];
    const float* fcw  = (const float*)d_in[10];
    const float* fcb  = (const float*)d_in[11];

    float* out   = (float*)d_out;
    float* probs = out;
    float* zvf   = (out_size >= 3 * TS) ? (out + 2ull * TS) : (float*)0;

    lstm_init_kernel<<<1, 32>>>();

    cudaLaunchConfig_t cfg = {};
    cfg.gridDim  = dim3(8, 1, 1);
    cfg.blockDim = dim3(384, 1, 1);
    cfg.dynamicSmemBytes = 0;
    cfg.stream = 0;
    cudaLaunchAttribute attrs[1];
    attrs[0].id = cudaLaunchAttributeClusterDimension;
    attrs[0].val.clusterDim.x = 2;
    attrs[0].val.clusterDim.y = 1;
    attrs[0].val.clusterDim.z = 1;
    cfg.attrs = attrs;
    cfg.numAttrs = 1;
    cudaLaunchKernelEx(&cfg, lstm_pipe_kernel,
                       x, h0, c0, wih0, wih1, wih2, wih3,
                       whh, bih, bhh, fcw, fcb, probs, zvf);
}

// round 17
// speedup vs baseline: 1.0756x; 1.0129x over previous
#include <cuda_runtime.h>
#include <cstdint>

#define TS 262144
#define HH 90
#define CHUNK 2

typedef unsigned long long u64t;

// inter-layer h streams (layers 0..2 produce) + progress counters
__device__ float g_hbuf[3ull * TS * HH];
__device__ unsigned g_cnt[3][2];

// ---------------- PTX helpers ----------------
__device__ __forceinline__ uint32_t smem_u32(const void* p) { return (uint32_t)__cvta_generic_to_shared(p); }
__device__ __forceinline__ uint32_t mapa_u32(uint32_t a, uint32_t r) {
    uint32_t o; asm("mapa.shared::cluster.u32 %0,%1,%2;" : "=r"(o) : "r"(a), "r"(r)); return o;
}
__device__ __forceinline__ uint32_t ctarank()  { uint32_t r; asm("mov.u32 %0, %%cluster_ctarank;"  : "=r"(r)); return r; }
__device__ __forceinline__ uint32_t nctarank() { uint32_t r; asm("mov.u32 %0, %%cluster_nctarank;" : "=r"(r)); return r; }
__device__ __forceinline__ void fma2(u64t& d, u64t a, u64t b) {
    asm("fma.rn.f32x2 %0,%1,%2,%0;" : "+l"(d) : "l"(a), "l"(b));
}
__device__ __forceinline__ float2 up64(u64t v) {
    float2 r; asm("mov.b64 {%0,%1},%2;" : "=f"(r.x), "=f"(r.y) : "l"(v)); return r;
}
__device__ __forceinline__ u64t pk64(float x, float y) {
    u64t v; asm("mov.b64 %0,{%1,%2};" : "=l"(v) : "f"(x), "f"(y)); return v;
}
__device__ __forceinline__ unsigned ld_acq(const unsigned* p) {
    unsigned v; asm volatile("ld.global.acquire.gpu.b32 %0,[%1];" : "=r"(v) : "l"(p) : "memory"); return v;
}
__device__ __forceinline__ void st_rel(unsigned* p, unsigned v) {
    asm volatile("st.global.release.gpu.b32 [%0],%1;" :: "l"(p), "r"(v) : "memory");
}
__device__ __forceinline__ void st_remote(uint32_t a, float v) {
    asm volatile("st.shared::cluster.f32 [%0],%1;" :: "r"(a), "f"(v) : "memory");
}
// acquire-poll of a LOCAL smem flag written remotely with release (no HW sleep!)
__device__ __forceinline__ unsigned ld_acq_sh(uint32_t a) {
    unsigned v;
    asm volatile("ld.acquire.cluster.shared::cta.b32 %0,[%1];" : "=r"(v) : "r"(a) : "memory");
    return v;
}
// release-store of step counter into PEER's smem flag (cumulative over prior bar.sync)
__device__ __forceinline__ void st_rel_sh_remote(uint32_t a, unsigned v) {
    asm volatile("st.release.cluster.shared::cluster.b32 [%0],%1;" :: "r"(a), "r"(v) : "memory");
}
// bounded flag poll
__device__ __forceinline__ bool flag_wait(uint32_t a, unsigned need) {
    for (unsigned i = 0; i < (1u << 24); i++) {
        if (ld_acq_sh(a) >= need) return true;
    }
    return false;
}
// bounded acquire-counter spin (global, inter-layer)
__device__ __forceinline__ bool spin_ge(const unsigned* p, unsigned need, unsigned& avail) {
    for (unsigned i = 0; i < (1u << 22); i++) {
        avail = ld_acq(p);
        if (avail >= need) return true;
    }
    return false;
}
__device__ __forceinline__ float sigf(float x)   { return 1.f / (1.f + __expf(-x)); }
__device__ __forceinline__ float tanhf_(float x) { return 1.f - 2.f / (__expf(2.f * x) + 1.f); }

// ---------------- per-layer persistent stage (2-CTA cluster, K-split GEMV) ----------------
// 384 threads: 0..179   = khalf0 rows 0..179 (input slice [0,48))
//              180..359 = khalf1 rows 0..179 (input slice [48,96))
//              360..383 = prefetch warp (off the GEMV critical path)
template<int LAYER>
__device__ void run_layer(
    const float* __restrict__ x_in,
    const float* __restrict__ h0, const float* __restrict__ c0,
    const float* __restrict__ wih, const float* __restrict__ whh,
    const float* __restrict__ bih, const float* __restrict__ bhh,
    const float* __restrict__ fcw, const float* __restrict__ fcb,
    float* probs, float* zvf)
{
    constexpr bool L0 = (LAYER == 0);
    constexpr bool LL = (LAYER == 3);
    constexpr int KIN  = L0 ? 6 : HH;
    constexpr int NPXH = L0 ? 3 : 24;   // packed x-weight pairs per thread (per K-half)
    constexpr int NW   = NPXH + 24;

    __shared__ __align__(16) float h_sm[2][96];
    __shared__ __align__(16) float x_sm[2][96];   // layers >= 1
    __shared__ __align__(16) float xr[4][8];      // layer 0 ring
    __shared__ float g2[2][184];                  // K-half partials
    __shared__ __align__(16) float fcw_sm[2][96];
    __shared__ float fcb_sm[2];
    __shared__ unsigned hflag;                    // monotonic step flag (remote-released)
    __shared__ int s_dead;

    const int tid  = (int)threadIdx.x;
    const int half = (int)ctarank();
    const int peer = half ^ 1;
    const int e0   = half * 45;
    const uint32_t flag_local = smem_u32(&hflag);
    const uint32_t flag_peer  = mapa_u32(flag_local, (uint32_t)peer);

    if (tid == 0) { s_dead = 0; hflag = 0u; }

    const bool  isg   = (tid < 360);
    const int   r     = isg ? (tid < 180 ? tid : tid - 180) : 0;  // row within CTA
    const int   khalf = (tid >= 180 && tid < 360) ? 1 : 0;
    const int   kbase = khalf * 48;                               // float offset of slice

    // ---- weights into registers: one gate-row K-half per thread ----
    u64t wk[NW];
    float bias = 0.f, c = 0.f;
    if (isg) {
        const int row = (r / 45) * HH + e0 + (r % 45);
#pragma unroll
        for (int p = 0; p < NPXH; p++) {
            int col0 = (L0 ? 0 : kbase) + 2 * p;       // L0: khalf1 gets zeros
            float a = (!(L0 && khalf) && col0     < KIN) ? wih[row * KIN + col0]     : 0.f;
            float b = (!(L0 && khalf) && col0 + 1 < KIN) ? wih[row * KIN + col0 + 1] : 0.f;
            wk[p] = pk64(a, b);
        }
#pragma unroll
        for (int p = 0; p < 24; p++) {
            int col0 = kbase + 2 * p;
            float a = (col0     < HH) ? whh[row * HH + col0]     : 0.f;
            float b = (col0 + 1 < HH) ? whh[row * HH + col0 + 1] : 0.f;
            wk[NPXH + p] = pk64(a, b);
        }
        bias = (khalf == 0) ? (bih[row] + bhh[row]) : 0.f;
    }
    if (tid < 45) c = c0[LAYER * HH + e0 + tid];

    // ---- smem zero/const init (epoch 1) ----
    if (tid < 96) {
        h_sm[0][tid] = (tid < HH) ? h0[LAYER * HH + tid] : 0.f;
        h_sm[1][tid] = 0.f;
        x_sm[0][tid] = 0.f; x_sm[1][tid] = 0.f;
        fcw_sm[0][tid] = 0.f; fcw_sm[1][tid] = 0.f;
    }
    if (tid < 32) ((float*)xr)[tid] = 0.f;
    if (LL && half == 0) {
        if (tid < HH) { fcw_sm[0][tid] = fcw[tid]; fcw_sm[1][tid] = fcw[HH + tid]; }
        if (tid < 2)  fcb_sm[tid] = fcb[tid];
    }
    __syncthreads();   // order zero-init before prologue writes below

    const float* hsrc = L0 ? (const float*)0 : (g_hbuf + (size_t)(LAYER - 1) * TS * HH);
    float*       hdst = LL ? (float*)0       : (g_hbuf + (size_t)LAYER * TS * HH);

    // prefetch warp state
    const int  q   = tid - 360;               // 0..23 when prefetch
    const bool pfw = (q >= 0);
    unsigned avail0 = 0, avail1 = 0;
    float pending = 0.f, nxt0 = 0.f, nxt1 = 0.f, nxt2 = 0.f, nxt3 = 0.f;

    if (L0) {
        // ring prologue (epoch 2): slots 0..3 <- x_0..x_3, pending <- x_4
        if (tid >= 96 && tid < 120) {
            int s = (tid - 96) / 6, k2 = (tid - 96) % 6;
            xr[s][k2] = x_in[(size_t)s * 6 + k2];
        }
        if (pfw && q < 6) pending = x_in[(size_t)4 * 6 + q];
    } else {
        if (tid < HH) {
            const unsigned* c0p = &g_cnt[LAYER - 1][(tid < 45) ? 0 : 1];
            unsigned a0 = 0;
            if (!spin_ge(c0p, 1u, a0)) s_dead = 1;
            x_sm[0][tid] = hsrc[tid];
        }
    }

    __syncthreads();
    asm volatile("barrier.cluster.arrive.aligned;" ::: "memory");
    asm volatile("barrier.cluster.wait.aligned;" ::: "memory");

    for (int t = 0; t < TS; t++) {
        const int buf = t & 1;
        const int nb  = buf ^ 1;

        // ---- prefetch warp: issue loads for x_{t+1} (L>=1) / x_{t+5} (L0) ----
        if (pfw) {
            if (!L0) {
                if (t + 1 < TS) {
                    const unsigned need = (unsigned)(t + 2);
                    if (!s_dead) {
                        if (avail0 < need && !spin_ge(&g_cnt[LAYER - 1][0], need, avail0)) s_dead = 1;
                        if (avail1 < need && !spin_ge(&g_cnt[LAYER - 1][1], need, avail1)) s_dead = 1;
                    }
                    const float* src = hsrc + (size_t)(t + 1) * HH;
                    nxt0 = src[q];
                    nxt1 = src[24 + q];
                    nxt2 = src[48 + q];
                    if (q < 18) nxt3 = src[72 + q];
                }
            } else {
                if (q < 6 && t + 5 < TS) nxt0 = x_in[(size_t)(t + 5) * 6 + q];
            }
        }

        u64t acc0 = 0ull, acc1 = 0ull, acc2 = 0ull, acc3 = 0ull;

        // ---- x-part (no h dependency; hides peer's DSMEM exchange) ----
        if (isg) {
            if (L0) {
                const u64t* xv = (const u64t*)xr[t & 3];
#pragma unroll
                for (int p = 0; p < 3; p++) fma2(acc0, wk[p], xv[p]);
            } else {
                const ulonglong2* xv = (const ulonglong2*)&x_sm[buf][kbase];
#pragma unroll
                for (int qq = 0; qq < 12; qq++) {
                    ulonglong2 v = xv[qq];
                    if ((qq & 1) == 0) { fma2(acc0, wk[2 * qq], v.x); fma2(acc1, wk[2 * qq + 1], v.y); }
                    else               { fma2(acc2, wk[2 * qq], v.x); fma2(acc3, wk[2 * qq + 1], v.y); }
                }
            }
        }

        // ---- wait for h_{t-1} exchange: poll local flag (NO mbarrier sleep) ----
        if (t && !s_dead) {
            if (!flag_wait(flag_local, (unsigned)t)) s_dead = 1;
        }

        // ---- h-part + partial write ----
        if (isg) {
            const ulonglong2* hv = (const ulonglong2*)&h_sm[buf][kbase];
#pragma unroll
            for (int qq = 0; qq < 12; qq++) {
                ulonglong2 v = hv[qq];
                if ((qq & 1) == 0) { fma2(acc0, wk[NPXH + 2 * qq], v.x); fma2(acc1, wk[NPXH + 2 * qq + 1], v.y); }
                else               { fma2(acc2, wk[NPXH + 2 * qq], v.x); fma2(acc3, wk[NPXH + 2 * qq + 1], v.y); }
            }
            float2 s0 = up64(acc0), s1 = up64(acc1), s2 = up64(acc2), s3 = up64(acc3);
            g2[khalf][r] = bias + ((s0.x + s0.y) + (s1.x + s1.y))
                                + ((s2.x + s2.y) + (s3.x + s3.y));
        }
        __syncthreads();

        // ---- combine: threads 0..44 own h/c elements [e0, e0+45) ----
        if (tid < 45) {
            float gi = g2[0][tid]        + g2[1][tid];
            float gf = g2[0][45 + tid]   + g2[1][45 + tid];
            float gg = g2[0][90 + tid]   + g2[1][90 + tid];
            float go = g2[0][135 + tid]  + g2[1][135 + tid];
            float iv = sigf(gi), fv = sigf(gf), gv = tanhf_(gg), ov = sigf(go);
            c = fv * c + iv * gv;
            float h = ov * tanhf_(c);
            h_sm[nb][e0 + tid] = h;
            st_remote(mapa_u32(smem_u32(&h_sm[nb][e0 + tid]), (uint32_t)peer), h);
            if (!LL) hdst[(size_t)t * HH + e0 + tid] = h;
        }

        // ---- FC + softmax + argmax on h_{t-1} (layer 3, CTA 0, warp 2) ----
        if (LL && half == 0 && t >= 1 && tid >= 64 && tid < 96) {
            const int j = tid - 64;
            const float* hb = h_sm[buf];
            float p0 = 0.f, p1 = 0.f;
#pragma unroll
            for (int kk = 0; kk < 3; kk++) {
                int k = j + 32 * kk;
                float hv = hb[k];
                p0 = fmaf(fcw_sm[0][k], hv, p0);
                p1 = fmaf(fcw_sm[1][k], hv, p1);
            }
#pragma unroll
            for (int off = 16; off; off >>= 1) {
                p0 += __shfl_down_sync(0xffffffffu, p0, off);
                p1 += __shfl_down_sync(0xffffffffu, p1, off);
            }
            if (j == 0) {
                float l0 = p0 + fcb_sm[0], l1 = p1 + fcb_sm[1];
                float m = fmaxf(l0, l1);
                float ea = __expf(l0 - m), eb = __expf(l1 - m);
                float inv = 1.f / (ea + eb);
                float2 pr; pr.x = ea * inv; pr.y = eb * inv;
                *(float2*)(probs + 2 * (size_t)(t - 1)) = pr;
                if (zvf) zvf[t - 1] = (l1 > l0) ? 1.f : 0.f;
            }
        }

        // ---- prefetch store ----
        if (pfw) {
            if (!L0) {
                if (t + 1 < TS) {
                    x_sm[nb][q]      = nxt0;
                    x_sm[nb][24 + q] = nxt1;
                    x_sm[nb][48 + q] = nxt2;
                    if (q < 18) x_sm[nb][72 + q] = nxt3;
                }
            } else {
                if (q < 6) {
                    if (t + 4 < TS) xr[t & 3][q] = pending;
                    pending = nxt0;
                }
            }
        }
        __syncthreads();

        // Release peer only after ALL step-t reads (incl. FC warp) are done.
        // bar.sync gives happens-before for the 45 combine threads' remote h-stores;
        // this single release store is cumulative over them.
        if (tid == 0) st_rel_sh_remote(flag_peer, (unsigned)(t + 1));

        // ---- publish progress to consumer layer (chunked) ----
        if (!LL && tid == 0 && (t & (CHUNK - 1)) == (CHUNK - 1))
            st_rel(&g_cnt[LAYER][half], (unsigned)(t + 1));
    }

    // final FC for h_{T-1}
    if (LL && half == 0) {
        if (!s_dead) flag_wait(flag_local, (unsigned)TS);
        if (tid >= 64 && tid < 96) {
            const int j = tid - 64;
            const float* hb = h_sm[TS & 1];
            float p0 = 0.f, p1 = 0.f;
#pragma unroll
            for (int kk = 0; kk < 3; kk++) {
                int k = j + 32 * kk;
                float hv = hb[k];
                p0 = fmaf(fcw_sm[0][k], hv, p0);
                p1 = fmaf(fcw_sm[1][k], hv, p1);
            }
#pragma unroll
            for (int off = 16; off; off >>= 1) {
                p0 += __shfl_down_sync(0xffffffffu, p0, off);
                p1 += __shfl_down_sync(0xffffffffu, p1, off);
            }
            if (j == 0) {
                float l0 = p0 + fcb_sm[0], l1 = p1 + fcb_sm[1];
                float m = fmaxf(l0, l1);
                float ea = __expf(l0 - m), eb = __expf(l1 - m);
                float inv = 1.f / (ea + eb);
                float2 pr; pr.x = ea * inv; pr.y = eb * inv;
                *(float2*)(probs + 2 * (size_t)(TS - 1)) = pr;
                if (zvf) zvf[TS - 1] = (l1 > l0) ? 1.f : 0.f;
            }
        }
    }
    asm volatile("barrier.cluster.arrive.aligned;" ::: "memory");
    asm volatile("barrier.cluster.wait.aligned;" ::: "memory");
}

// ---------------- kernels ----------------
__global__ void lstm_init_kernel() {
    if (threadIdx.x < 6) (&g_cnt[0][0])[threadIdx.x] = 0u;
}

__global__ void __cluster_dims__(2, 1, 1) __launch_bounds__(384, 1)
lstm_pipe_kernel(
    const float* __restrict__ x,
    const float* __restrict__ h0,  const float* __restrict__ c0,
    const float* __restrict__ wih0, const float* __restrict__ wih1,
    const float* __restrict__ wih2, const float* __restrict__ wih3,
    const float* __restrict__ whh,
    const float* __restrict__ bih, const float* __restrict__ bhh,
    const float* __restrict__ fcw, const float* __restrict__ fcb,
    float* probs, float* zvf)
{
    if (nctarank() != 2) return;   // clusters broken -> fast visible failure, no hang
    const int layer = (int)(blockIdx.x >> 1);
    if (layer == 0)
        run_layer<0>(x, h0, c0, wih0, whh + 0 * 360 * HH, bih + 0 * 360, bhh + 0 * 360,
                     fcw, fcb, probs, zvf);
    else if (layer == 1)
        run_layer<1>(x, h0, c0, wih1, whh + 1 * 360 * HH, bih + 1 * 360, bhh + 1 * 360,
                     fcw, fcb, probs, zvf);
    else if (layer == 2)
        run_layer<2>(x, h0, c0, wih2, whh + 2 * 360 * HH, bih + 2 * 360, bhh + 2 * 360,
                     fcw, fcb, probs, zvf);
    else
        run_layer<3>(x, h0, c0, wih3, whh + 3 * 360 * HH, bih + 3 * 360, bhh + 3 * 360,
                     fcw, fcb, probs, zvf);
}

extern "C" void kernel_launch(void* const* d_in, const int* in_sizes, int n_in,
                              void* d_out, int out_size) {
    const float* x    = (const float*)d_in[0];
    const float* h0   = (const float*)d_in[1];
    const float* c0   = (const float*)d_in[2];
    const float* wih0 = (const float*)d_in[3];
    const float* wih1 = (const float*)d_in[4];
    const float* wih2 = (const float*)d_in[5];
    const float* wih3 = (const float*)d_in[6];
    const float* whh  = (const float*)d_in[7];
    const float* bih  = (const float*)d_in[8];
    const float* bhh  = (const float*)d_in[9];
    const float* fcw  = (const float*)d_in[10];
    const float* fcb  = (const float*)d_in[11];

    float* out   = (float*)d_out;
    float* probs = out;
    float* zvf   = (out_size >= 3 * TS) ? (out + 2ull * TS) : (float*)0;

    lstm_init_kernel<<<1, 32>>>();

    cudaLaunchConfig_t cfg = {};
    cfg.gridDim  = dim3(8, 1, 1);
    cfg.blockDim = dim3(384, 1, 1);
    cfg.dynamicSmemBytes = 0;
    cfg.stream = 0;
    cudaLaunchAttribute attrs[1];
    attrs[0].id = cudaLaunchAttributeClusterDimension;
    attrs[0].val.clusterDim.x = 2;
    attrs[0].val.clusterDim.y = 1;
    attrs[0].val.clusterDim.z = 1;
    cfg.attrs = attrs;
    cfg.numAttrs = 1;
    cudaLaunchKernelEx(&cfg, lstm_pipe_kernel,
                       x, h0, c0, wih0, wih1, wih2, wih3,
                       whh, bih, bhh, fcw, fcb, probs, zvf);
}